// round 3
// baseline (speedup 1.0000x reference)
#include <cuda_runtime.h>
#include <math.h>

#define FULL 0xffffffffu

static constexpr int B  = 64;
static constexpr int T  = 512;
static constexpr int D  = 768;
static constexpr int LA = 2;   // CRF1 labels
static constexpr int LB = 9;   // CRF2 labels

// ---------------- device scratch ----------------
__device__ float g_logits1[B * T * LA];
__device__ float g_logits2[B * T * LB];
__device__ float g_ll1[B];
__device__ float g_ll2[B];
__device__ float g_c1[B];
__device__ float g_c2[B];
__device__ float g_cc[B];
__device__ int   g_ctr;   // zero at module load; reset by last block each launch

// ---------------- fused projection: logits = x@W + b --------------------
// warp computes 4 rows; lane covers d = k*128 + lane*4 (float4); 44 accumulators.
__global__ __launch_bounds__(256) void gemm_kernel(const float* __restrict__ x,
                                                   const float* __restrict__ W1,
                                                   const float* __restrict__ b1,
                                                   const float* __restrict__ W2,
                                                   const float* __restrict__ b2) {
    __shared__ float wT[11][768];
    __shared__ float bsh[11];
    int tid = threadIdx.x;
    for (int i = tid; i < 768 * 2; i += 256) wT[i & 1][i >> 1] = W1[i];
    for (int i = tid; i < 768 * 9; i += 256) { int d = i / 9; wT[2 + (i - d * 9)][d] = W2[i]; }
    if (tid < 2) bsh[tid] = b1[tid];
    else if (tid < 11) bsh[tid] = b2[tid - 2];
    __syncthreads();

    int warp = tid >> 5, lane = tid & 31;
    int row0 = (blockIdx.x * 8 + warp) * 4;

    float acc[4][11];
#pragma unroll
    for (int r = 0; r < 4; r++)
#pragma unroll
        for (int l = 0; l < 11; l++) acc[r][l] = 0.0f;

    const float4* xp = reinterpret_cast<const float4*>(x) + (size_t)row0 * 192 + lane;

#pragma unroll
    for (int k = 0; k < 6; k++) {
        float4 w[11];
#pragma unroll
        for (int l = 0; l < 11; l++)
            w[l] = *reinterpret_cast<const float4*>(&wT[l][k * 128 + lane * 4]);
#pragma unroll
        for (int r = 0; r < 4; r++) {
            float4 xv = xp[r * 192 + k * 32];
#pragma unroll
            for (int l = 0; l < 11; l++)
                acc[r][l] = fmaf(xv.x, w[l].x,
                           fmaf(xv.y, w[l].y,
                           fmaf(xv.z, w[l].z,
                           fmaf(xv.w, w[l].w, acc[r][l]))));
        }
    }

#pragma unroll
    for (int r = 0; r < 4; r++)
#pragma unroll
        for (int l = 0; l < 11; l++) {
            float v = acc[r][l];
#pragma unroll
            for (int o = 16; o; o >>= 1) v += __shfl_xor_sync(FULL, v, o);
            acc[r][l] = v;
        }

    if (lane == 0) {
#pragma unroll
        for (int r = 0; r < 4; r++) {
            int row = row0 + r;
            g_logits1[row * LA + 0] = acc[r][0] + bsh[0];
            g_logits1[row * LA + 1] = acc[r][1] + bsh[1];
#pragma unroll
            for (int l = 0; l < 9; l++) g_logits2[row * LB + l] = acc[r][2 + l] + bsh[2 + l];
        }
    }
}

// ---------------- CRF log-partition scan, LINEAR domain ------------------
// a_j holds alpha_j * 2^{-Zi}. Step: a_j = (sum_i a_i * E_ij) * el[t][j].
// No MUFU on the critical path. Exact power-of-2 renorm every 4 steps.
template <int L>
__device__ __forceinline__ float crf_lognorm_lin(const float* __restrict__ els,  // shared [T][L] = exp(logit)
                                                 const float* __restrict__ trans,
                                                 int sl) {
    const int j = threadIdx.x & 31;
    float E[L];
#pragma unroll
    for (int i = 0; i < L; i++) E[i] = (j < L) ? __expf(trans[i * L + j]) : 0.0f;

    float a = (j < L) ? els[j] : 0.0f;
    int Zi = 0;

    for (int t = 1; t < sl; ++t) {
        float el = (j < L) ? els[t * L + j] : 0.0f;   // LDS, issues early
        float s[L];
#pragma unroll
        for (int i = 0; i < L; i++) s[i] = __shfl_sync(FULL, a, i) * E[i];
#pragma unroll
        for (int st = 1; st < L; st <<= 1)
#pragma unroll
            for (int i = 0; i + st < L; i += 2 * st) s[i] += s[i + st];
        a = s[0] * el;
        if ((t & 3) == 0) {                            // exact renorm: shift by a0's exponent
            float r0 = __shfl_sync(FULL, a, 0);
            int eb = (__float_as_int(r0) >> 23) & 0xff;
            a *= __int_as_float((254 - eb) << 23);     // * 2^{127-eb}
            Zi += eb - 127;
        }
    }

    float v = a;
#pragma unroll
    for (int o = 16; o; o >>= 1) v += __shfl_xor_sync(FULL, v, o);
    return (float)Zi * 0.6931471805599453f + __logf(v);
}

// ---------------- Viterbi decode (one warp) ------------------------------
template <int L>
__device__ __forceinline__ void crf_decode_warp(const float* __restrict__ lgs,  // shared [T][L]
                                                const float* __restrict__ trans,
                                                int sl,
                                                unsigned char* __restrict__ bp_sh,   // [T][L]
                                                unsigned char* __restrict__ vit_sh)  // [T]
{
    const int j = threadIdx.x & 31;
    float Trow[L];
#pragma unroll
    for (int i = 0; i < L; i++) Trow[i] = (j < L) ? trans[i * L + j] : 0.0f;

    float v = (j < L) ? lgs[j] : -3.0e38f;

    for (int t = 1; t < sl; ++t) {
        float lv = (j < L) ? lgs[t * L + j] : 0.0f;
        float q[L];
#pragma unroll
        for (int i = 0; i < L; i++) q[i] = __shfl_sync(FULL, v, i) + Trow[i];
        float r[L];
#pragma unroll
        for (int i = 0; i < L; i++) r[i] = q[i];
#pragma unroll
        for (int st = 1; st < L; st <<= 1)
#pragma unroll
            for (int i = 0; i + st < L; i += st * 2) r[i] = fmaxf(r[i], r[i + st]);
        float m = r[0];
        int bp = 0;
#pragma unroll
        for (int i = L - 1; i >= 0; i--) bp = (q[i] == m) ? i : bp;  // first-max index
        if (j < L) bp_sh[t * L + j] = (unsigned char)bp;
        v = m + lv;
    }

    float q[L];
#pragma unroll
    for (int i = 0; i < L; i++) q[i] = __shfl_sync(FULL, v, i);
    float best = q[0];
    int last = 0;
#pragma unroll
    for (int i = 1; i < L; i++)
        if (q[i] > best) { best = q[i]; last = i; }

    for (int t = sl - 1 + j; t < T; t += 32) vit_sh[t] = (unsigned char)last;
    __syncwarp();

    if (j == 0) {
        int cur = last;
        for (int t = sl - 1; t >= 1; --t) {
            cur = bp_sh[t * L + cur];
            vit_sh[t - 1] = (unsigned char)cur;
        }
    }
    __syncwarp();
}

// ---------------- scan kernel: 1 block = 1 batch, 4 role warps -----------
// last block also does the final cross-batch reduction (fused final_kernel)
__global__ __launch_bounds__(128) void scan_kernel(const int* __restrict__ label,
                                                   const int* __restrict__ seqlen,
                                                   const float* __restrict__ trans1,
                                                   const float* __restrict__ trans2,
                                                   float* __restrict__ out,
                                                   int out_size) {
    __shared__ float lg1s[T * LA];
    __shared__ float lg2s[T * LB];
    __shared__ float el1s[T * LA];
    __shared__ float el2s[T * LB];
    __shared__ unsigned char bp1[T * LA];
    __shared__ unsigned char bp2[T * LB];
    __shared__ unsigned char vit1s[T];
    __shared__ unsigned char vit2s[T];
    __shared__ float sred[12];
    __shared__ int s_last;

    int b = blockIdx.x;
    int sl = seqlen[b];
    int wid = threadIdx.x >> 5;
    int lane = threadIdx.x & 31;
    const int* lab = label + b * T;

    {
        const float* lg1g = g_logits1 + b * T * LA;
        const float* lg2g = g_logits2 + b * T * LB;
        for (int i = threadIdx.x; i < T * LA; i += 128) {
            float v = lg1g[i]; lg1s[i] = v; el1s[i] = __expf(v);
        }
        for (int i = threadIdx.x; i < T * LB; i += 128) {
            float v = lg2g[i]; lg2s[i] = v; el2s[i] = __expf(v);
        }
    }
    __syncthreads();

    if (wid == 0) {
        float s = 0.0f;
        for (int t = lane; t < sl; t += 32) {
            int tg = (lab[t] > 0) ? 1 : 0;
            s += lg1s[t * LA + tg];
            if (t > 0) {
                int tp = (lab[t - 1] > 0) ? 1 : 0;
                s += trans1[tp * LA + tg];
            }
        }
#pragma unroll
        for (int o = 16; o; o >>= 1) s += __shfl_xor_sync(FULL, s, o);
        float ln = crf_lognorm_lin<LA>(el1s, trans1, sl);
        if (lane == 0) g_ll1[b] = s - ln;
    } else if (wid == 1) {
        crf_decode_warp<LA>(lg1s, trans1, sl, bp1, vit1s);
    } else if (wid == 2) {
        float s = 0.0f;
        for (int t = lane; t < sl; t += 32) {
            int tg = lab[t];
            s += lg2s[t * LB + tg];
            if (t > 0) {
                int tp = lab[t - 1];
                s += trans2[tp * LB + tg];
            }
        }
#pragma unroll
        for (int o = 16; o; o >>= 1) s += __shfl_xor_sync(FULL, s, o);
        float ln = crf_lognorm_lin<LB>(el2s, trans2, sl);
        if (lane == 0) g_ll2[b] = s - ln;
    } else {
        crf_decode_warp<LB>(lg2s, trans2, sl, bp2, vit2s);
    }
    __syncthreads();

    // fuse: viterbi = where(vit1==0, 0, vit2); accuracy partials
    float c1 = 0.0f, c2 = 0.0f, cc = 0.0f;
    for (int t = threadIdx.x; t < T; t += 128) {
        int v1 = vit1s[t];
        int v2 = vit2s[t];
        int lb = lab[t];
        int vv = (v1 == 0) ? 0 : v2;
        out[b * T + t] = (float)vv;
        if (t < sl) {
            c1 += (v1 == ((lb > 0) ? 1 : 0)) ? 1.0f : 0.0f;
            c2 += (v2 == lb) ? 1.0f : 0.0f;
            cc += (vv == lb) ? 1.0f : 0.0f;
        }
    }
#pragma unroll
    for (int o = 16; o; o >>= 1) {
        c1 += __shfl_xor_sync(FULL, c1, o);
        c2 += __shfl_xor_sync(FULL, c2, o);
        cc += __shfl_xor_sync(FULL, cc, o);
    }
    if (lane == 0) {
        sred[wid] = c1;
        sred[4 + wid] = c2;
        sred[8 + wid] = cc;
    }
    __syncthreads();
    if (threadIdx.x == 0) {
        g_c1[b] = sred[0] + sred[1] + sred[2] + sred[3];
        g_c2[b] = sred[4] + sred[5] + sred[6] + sred[7];
        g_cc[b] = sred[8] + sred[9] + sred[10] + sred[11];
        __threadfence();
        int v = atomicAdd(&g_ctr, 1);
        s_last = (v == B - 1) ? 1 : 0;
    }
    __syncthreads();

    // ---- fused final reduction: only the last-arriving block ----
    if (s_last) {
        __threadfence();
        int i = threadIdx.x;
        float vals[6] = {0, 0, 0, 0, 0, 0};
        if (i < B) {
            vals[0] = -g_ll1[i];
            vals[1] = -g_ll2[i];
            vals[2] = g_c1[i];
            vals[3] = g_c2[i];
            vals[4] = g_cc[i];
            vals[5] = (float)seqlen[i];
        }
#pragma unroll
        for (int k = 0; k < 6; k++)
#pragma unroll
            for (int o = 16; o; o >>= 1) vals[k] += __shfl_xor_sync(FULL, vals[k], o);
        __shared__ float sh2[2][6];
        if (i < B && (i & 31) == 0)
#pragma unroll
            for (int k = 0; k < 6; k++) sh2[i >> 5][k] = vals[k];
        __syncthreads();
        if (i == 0) {
            float S[6];
#pragma unroll
            for (int k = 0; k < 6; k++) S[k] = sh2[0][k] + sh2[1][k];
            float loss1 = S[0] / (float)B;
            float loss2 = S[1] / (float)B;
            float loss = (loss1 + 8.0f * loss2) / 9.0f;
            float tot = S[5];
            int base = out_size - 4;
            out[base + 0] = loss;
            out[base + 1] = S[2] / tot;
            out[base + 2] = S[3] / tot;
            out[base + 3] = S[4] / tot;
            g_ctr = 0;   // reset for next graph replay
        }
    }
}

// ---------------- launch -------------------------------------------------
extern "C" void kernel_launch(void* const* d_in, const int* in_sizes, int n_in,
                              void* d_out, int out_size) {
    const float* x      = (const float*)d_in[0];
    const int*   label  = (const int*)d_in[1];
    const int*   seqlen = (const int*)d_in[2];
    const float* W1     = (const float*)d_in[3];
    const float* b1     = (const float*)d_in[4];
    const float* W2     = (const float*)d_in[5];
    const float* b2     = (const float*)d_in[6];
    const float* trans1 = (const float*)d_in[7];
    const float* trans2 = (const float*)d_in[8];
    float* out = (float*)d_out;

    gemm_kernel<<<(B * T) / 32, 256>>>(x, W1, b1, W2, b2);
    scan_kernel<<<B, 128>>>(label, seqlen, trans1, trans2, out, out_size);
}

// round 4
// speedup vs baseline: 1.0049x; 1.0049x over previous
#include <cuda_runtime.h>
#include <math.h>

#define FULL 0xffffffffu

static constexpr int B  = 64;
static constexpr int T  = 512;
static constexpr int D  = 768;
static constexpr int LA = 2;   // CRF1 labels
static constexpr int LB = 9;   // CRF2 labels

// ---------------- device scratch ----------------
__device__ float g_logits1[B * T * LA];
__device__ float g_logits2[B * T * LB];
__device__ float g_ll1[B];
__device__ float g_ll2[B];
__device__ float g_c1[B];
__device__ float g_c2[B];
__device__ float g_cc[B];
__device__ int   g_ctr;   // zero at module load; reset by last block each launch

// ---------------- fused projection: logits = x@W + b --------------------
// warp computes 4 rows; lane covers d = k*128 + lane*4 (float4); 44 accumulators.
__global__ __launch_bounds__(256) void gemm_kernel(const float* __restrict__ x,
                                                   const float* __restrict__ W1,
                                                   const float* __restrict__ b1,
                                                   const float* __restrict__ W2,
                                                   const float* __restrict__ b2) {
    __shared__ float wT[11][768];
    __shared__ float bsh[11];
    int tid = threadIdx.x;
    for (int i = tid; i < 768 * 2; i += 256) wT[i & 1][i >> 1] = W1[i];
    for (int i = tid; i < 768 * 9; i += 256) { int d = i / 9; wT[2 + (i - d * 9)][d] = W2[i]; }
    if (tid < 2) bsh[tid] = b1[tid];
    else if (tid < 11) bsh[tid] = b2[tid - 2];
    __syncthreads();

    int warp = tid >> 5, lane = tid & 31;
    int row0 = (blockIdx.x * 8 + warp) * 4;

    float acc[4][11];
#pragma unroll
    for (int r = 0; r < 4; r++)
#pragma unroll
        for (int l = 0; l < 11; l++) acc[r][l] = 0.0f;

    const float4* xp = reinterpret_cast<const float4*>(x) + (size_t)row0 * 192 + lane;

#pragma unroll
    for (int k = 0; k < 6; k++) {
        float4 w[11];
#pragma unroll
        for (int l = 0; l < 11; l++)
            w[l] = *reinterpret_cast<const float4*>(&wT[l][k * 128 + lane * 4]);
#pragma unroll
        for (int r = 0; r < 4; r++) {
            float4 xv = xp[r * 192 + k * 32];
#pragma unroll
            for (int l = 0; l < 11; l++)
                acc[r][l] = fmaf(xv.x, w[l].x,
                           fmaf(xv.y, w[l].y,
                           fmaf(xv.z, w[l].z,
                           fmaf(xv.w, w[l].w, acc[r][l]))));
        }
    }

#pragma unroll
    for (int r = 0; r < 4; r++)
#pragma unroll
        for (int l = 0; l < 11; l++) {
            float v = acc[r][l];
#pragma unroll
            for (int o = 16; o; o >>= 1) v += __shfl_xor_sync(FULL, v, o);
            acc[r][l] = v;
        }

    if (lane == 0) {
#pragma unroll
        for (int r = 0; r < 4; r++) {
            int row = row0 + r;
            g_logits1[row * LA + 0] = acc[r][0] + bsh[0];
            g_logits1[row * LA + 1] = acc[r][1] + bsh[1];
#pragma unroll
            for (int l = 0; l < 9; l++) g_logits2[row * LB + l] = acc[r][2 + l] + bsh[2 + l];
        }
    }
}

// ---------------- CRF log-partition scan, LINEAR domain ------------------
// a_j holds alpha_j * 2^{-Zi}. Step: a_j = (sum_i a_i * E_ij) * el[t][j].
// No MUFU on the critical path. Exact power-of-2 renorm every 4 steps.
template <int L>
__device__ __forceinline__ float crf_lognorm_lin(const float* __restrict__ els,  // shared [T][L] = exp(logit)
                                                 const float* __restrict__ trans,
                                                 int sl) {
    const int j = threadIdx.x & 31;
    float E[L];
#pragma unroll
    for (int i = 0; i < L; i++) E[i] = (j < L) ? __expf(trans[i * L + j]) : 0.0f;

    float a = (j < L) ? els[j] : 0.0f;
    int Zi = 0;

    for (int t = 1; t < sl; ++t) {
        float el = (j < L) ? els[t * L + j] : 0.0f;   // LDS, issues early
        float s[L];
#pragma unroll
        for (int i = 0; i < L; i++) s[i] = __shfl_sync(FULL, a, i) * E[i];
#pragma unroll
        for (int st = 1; st < L; st <<= 1)
#pragma unroll
            for (int i = 0; i + st < L; i += 2 * st) s[i] += s[i + st];
        a = s[0] * el;
        if ((t & 3) == 0) {                            // exact renorm: shift by a0's exponent
            float r0 = __shfl_sync(FULL, a, 0);
            int eb = (__float_as_int(r0) >> 23) & 0xff;
            a *= __int_as_float((254 - eb) << 23);     // * 2^{127-eb}
            Zi += eb - 127;
        }
    }

    float v = a;
#pragma unroll
    for (int o = 16; o; o >>= 1) v += __shfl_xor_sync(FULL, v, o);
    return (float)Zi * 0.6931471805599453f + __logf(v);
}

// ---------------- Viterbi decode (one warp) ------------------------------
template <int L>
__device__ __forceinline__ void crf_decode_warp(const float* __restrict__ lgs,  // shared [T][L]
                                                const float* __restrict__ trans,
                                                int sl,
                                                unsigned char* __restrict__ bp_sh,   // [T][L]
                                                unsigned char* __restrict__ vit_sh)  // [T]
{
    const int j = threadIdx.x & 31;
    float Trow[L];
#pragma unroll
    for (int i = 0; i < L; i++) Trow[i] = (j < L) ? trans[i * L + j] : 0.0f;

    float v = (j < L) ? lgs[j] : -3.0e38f;

    for (int t = 1; t < sl; ++t) {
        float lv = (j < L) ? lgs[t * L + j] : 0.0f;
        float q[L];
#pragma unroll
        for (int i = 0; i < L; i++) q[i] = __shfl_sync(FULL, v, i) + Trow[i];
        float r[L];
#pragma unroll
        for (int i = 0; i < L; i++) r[i] = q[i];
#pragma unroll
        for (int st = 1; st < L; st <<= 1)
#pragma unroll
            for (int i = 0; i + st < L; i += st * 2) r[i] = fmaxf(r[i], r[i + st]);
        float m = r[0];
        int bp = 0;
#pragma unroll
        for (int i = L - 1; i >= 0; i--) bp = (q[i] == m) ? i : bp;  // first-max index
        if (j < L) bp_sh[t * L + j] = (unsigned char)bp;
        v = m + lv;
    }

    float q[L];
#pragma unroll
    for (int i = 0; i < L; i++) q[i] = __shfl_sync(FULL, v, i);
    float best = q[0];
    int last = 0;
#pragma unroll
    for (int i = 1; i < L; i++)
        if (q[i] > best) { best = q[i]; last = i; }

    for (int t = sl - 1 + j; t < T; t += 32) vit_sh[t] = (unsigned char)last;
    __syncwarp();

    if (j == 0) {
        int cur = last;
        for (int t = sl - 1; t >= 1; --t) {
            cur = bp_sh[t * L + cur];
            vit_sh[t - 1] = (unsigned char)cur;
        }
    }
    __syncwarp();
}

// ---------------- scan kernel: 1 block = 1 batch, 4 role warps -----------
// last block also does the final cross-batch reduction (fused final_kernel)
__global__ __launch_bounds__(128) void scan_kernel(const int* __restrict__ label,
                                                   const int* __restrict__ seqlen,
                                                   const float* __restrict__ trans1,
                                                   const float* __restrict__ trans2,
                                                   float* __restrict__ out,
                                                   int out_size) {
    __shared__ float lg1s[T * LA];
    __shared__ float lg2s[T * LB];
    __shared__ float el1s[T * LA];
    __shared__ float el2s[T * LB];
    __shared__ unsigned char bp1[T * LA];
    __shared__ unsigned char bp2[T * LB];
    __shared__ unsigned char vit1s[T];
    __shared__ unsigned char vit2s[T];
    __shared__ float sred[12];
    __shared__ int s_last;

    int b = blockIdx.x;
    int sl = seqlen[b];
    int wid = threadIdx.x >> 5;
    int lane = threadIdx.x & 31;
    const int* lab = label + b * T;

    {
        const float* lg1g = g_logits1 + b * T * LA;
        const float* lg2g = g_logits2 + b * T * LB;
        for (int i = threadIdx.x; i < T * LA; i += 128) {
            float v = lg1g[i]; lg1s[i] = v; el1s[i] = __expf(v);
        }
        for (int i = threadIdx.x; i < T * LB; i += 128) {
            float v = lg2g[i]; lg2s[i] = v; el2s[i] = __expf(v);
        }
    }
    __syncthreads();

    if (wid == 0) {
        float s = 0.0f;
        for (int t = lane; t < sl; t += 32) {
            int tg = (lab[t] > 0) ? 1 : 0;
            s += lg1s[t * LA + tg];
            if (t > 0) {
                int tp = (lab[t - 1] > 0) ? 1 : 0;
                s += trans1[tp * LA + tg];
            }
        }
#pragma unroll
        for (int o = 16; o; o >>= 1) s += __shfl_xor_sync(FULL, s, o);
        float ln = crf_lognorm_lin<LA>(el1s, trans1, sl);
        if (lane == 0) g_ll1[b] = s - ln;
    } else if (wid == 1) {
        crf_decode_warp<LA>(lg1s, trans1, sl, bp1, vit1s);
    } else if (wid == 2) {
        float s = 0.0f;
        for (int t = lane; t < sl; t += 32) {
            int tg = lab[t];
            s += lg2s[t * LB + tg];
            if (t > 0) {
                int tp = lab[t - 1];
                s += trans2[tp * LB + tg];
            }
        }
#pragma unroll
        for (int o = 16; o; o >>= 1) s += __shfl_xor_sync(FULL, s, o);
        float ln = crf_lognorm_lin<LB>(el2s, trans2, sl);
        if (lane == 0) g_ll2[b] = s - ln;
    } else {
        crf_decode_warp<LB>(lg2s, trans2, sl, bp2, vit2s);
    }
    __syncthreads();

    // fuse: viterbi = where(vit1==0, 0, vit2); accuracy partials
    float c1 = 0.0f, c2 = 0.0f, cc = 0.0f;
    for (int t = threadIdx.x; t < T; t += 128) {
        int v1 = vit1s[t];
        int v2 = vit2s[t];
        int lb = lab[t];
        int vv = (v1 == 0) ? 0 : v2;
        out[b * T + t] = (float)vv;
        if (t < sl) {
            c1 += (v1 == ((lb > 0) ? 1 : 0)) ? 1.0f : 0.0f;
            c2 += (v2 == lb) ? 1.0f : 0.0f;
            cc += (vv == lb) ? 1.0f : 0.0f;
        }
    }
#pragma unroll
    for (int o = 16; o; o >>= 1) {
        c1 += __shfl_xor_sync(FULL, c1, o);
        c2 += __shfl_xor_sync(FULL, c2, o);
        cc += __shfl_xor_sync(FULL, cc, o);
    }
    if (lane == 0) {
        sred[wid] = c1;
        sred[4 + wid] = c2;
        sred[8 + wid] = cc;
    }
    __syncthreads();
    if (threadIdx.x == 0) {
        g_c1[b] = sred[0] + sred[1] + sred[2] + sred[3];
        g_c2[b] = sred[4] + sred[5] + sred[6] + sred[7];
        g_cc[b] = sred[8] + sred[9] + sred[10] + sred[11];
        __threadfence();
        int v = atomicAdd(&g_ctr, 1);
        s_last = (v == B - 1) ? 1 : 0;
    }
    __syncthreads();

    // ---- fused final reduction: only the last-arriving block ----
    if (s_last) {
        __threadfence();
        int i = threadIdx.x;
        float vals[6] = {0, 0, 0, 0, 0, 0};
        if (i < B) {
            vals[0] = -g_ll1[i];
            vals[1] = -g_ll2[i];
            vals[2] = g_c1[i];
            vals[3] = g_c2[i];
            vals[4] = g_cc[i];
            vals[5] = (float)seqlen[i];
        }
#pragma unroll
        for (int k = 0; k < 6; k++)
#pragma unroll
            for (int o = 16; o; o >>= 1) vals[k] += __shfl_xor_sync(FULL, vals[k], o);
        __shared__ float sh2[2][6];
        if (i < B && (i & 31) == 0)
#pragma unroll
            for (int k = 0; k < 6; k++) sh2[i >> 5][k] = vals[k];
        __syncthreads();
        if (i == 0) {
            float S[6];
#pragma unroll
            for (int k = 0; k < 6; k++) S[k] = sh2[0][k] + sh2[1][k];
            float loss1 = S[0] / (float)B;
            float loss2 = S[1] / (float)B;
            float loss = (loss1 + 8.0f * loss2) / 9.0f;
            float tot = S[5];
            int base = out_size - 4;
            out[base + 0] = loss;
            out[base + 1] = S[2] / tot;
            out[base + 2] = S[3] / tot;
            out[base + 3] = S[4] / tot;
            g_ctr = 0;   // reset for next graph replay
        }
    }
}

// ---------------- launch -------------------------------------------------
extern "C" void kernel_launch(void* const* d_in, const int* in_sizes, int n_in,
                              void* d_out, int out_size) {
    const float* x      = (const float*)d_in[0];
    const int*   label  = (const int*)d_in[1];
    const int*   seqlen = (const int*)d_in[2];
    const float* W1     = (const float*)d_in[3];
    const float* b1     = (const float*)d_in[4];
    const float* W2     = (const float*)d_in[5];
    const float* b2     = (const float*)d_in[6];
    const float* trans1 = (const float*)d_in[7];
    const float* trans2 = (const float*)d_in[8];
    float* out = (float*)d_out;

    gemm_kernel<<<(B * T) / 32, 256>>>(x, W1, b1, W2, b2);
    scan_kernel<<<B, 128>>>(label, seqlen, trans1, trans2, out, out_size);
}

// round 5
// speedup vs baseline: 1.2325x; 1.2264x over previous
#include <cuda_runtime.h>
#include <math.h>
#define FULL 0xffffffffu
#define M9 0x1ffu

static constexpr int B=64,T=512,D=768;

__device__ float g_lg1[B*T*2];
__device__ float g_lg2[B*T*9];
__device__ float g_ll1[B],g_ll2[B],g_c1[B],g_c2[B],g_cc[B];
__device__ int g_ctr;

__device__ __forceinline__ unsigned long long ffma2(unsigned long long a,unsigned long long b,unsigned long long c){
    unsigned long long r; asm("fma.rn.f32x2 %0,%1,%2,%3;":"=l"(r):"l"(a),"l"(b),"l"(c)); return r;
}

__global__ __launch_bounds__(256) void gemm_kernel(const float* __restrict__ x,const float* __restrict__ W1,
    const float* __restrict__ b1,const float* __restrict__ W2,const float* __restrict__ b2){
    __shared__ float wT[11][768]; __shared__ float bsh[11];
    int tid=threadIdx.x;
    for(int i=tid;i<768*2;i+=256) wT[i&1][i>>1]=W1[i];
    for(int i=tid;i<768*9;i+=256){int d=i/9; wT[2+(i-d*9)][d]=W2[i];}
    if(tid<2)bsh[tid]=b1[tid]; else if(tid<11)bsh[tid]=b2[tid-2];
    __syncthreads();
    int warp=tid>>5,lane=tid&31;
    int row0=(blockIdx.x*8+warp)*4;
    unsigned long long acc[4][11];
#pragma unroll
    for(int r=0;r<4;r++)
#pragma unroll
        for(int l=0;l<11;l++) acc[r][l]=0ull;
    const ulonglong2* xp=reinterpret_cast<const ulonglong2*>(x+(size_t)row0*D)+lane;
#pragma unroll
    for(int k=0;k<6;k++){
        ulonglong2 w[11];
#pragma unroll
        for(int l=0;l<11;l++) w[l]=*reinterpret_cast<const ulonglong2*>(&wT[l][k*128+lane*4]);
#pragma unroll
        for(int r=0;r<4;r++){
            ulonglong2 xv=xp[r*192+k*32];
#pragma unroll
            for(int l=0;l<11;l++){
                acc[r][l]=ffma2(xv.x,w[l].x,acc[r][l]);
                acc[r][l]=ffma2(xv.y,w[l].y,acc[r][l]);
            }
        }
    }
    float red[4][11];
#pragma unroll
    for(int r=0;r<4;r++)
#pragma unroll
        for(int l=0;l<11;l++){
            unsigned long long a=acc[r][l];
            float v=__uint_as_float((unsigned)(a&0xffffffffull))+__uint_as_float((unsigned)(a>>32));
#pragma unroll
            for(int o=16;o;o>>=1) v+=__shfl_xor_sync(FULL,v,o);
            red[r][l]=v;
        }
    if(lane==0){
#pragma unroll
        for(int r=0;r<4;r++){
            int row=row0+r;
            g_lg1[row*2+0]=red[r][0]+bsh[0];
            g_lg1[row*2+1]=red[r][1]+bsh[1];
#pragma unroll
            for(int l=0;l<9;l++) g_lg2[row*9+l]=red[r][2+l]+bsh[2+l];
        }
    }
}

__global__ __launch_bounds__(256) void scan_kernel(const int* __restrict__ label,const int* __restrict__ seqlen,
    const float* __restrict__ trans1,const float* __restrict__ trans2,float* __restrict__ out,int out_size){
    extern __shared__ char sm[];
    float* lg2s=(float*)sm;                       // 18432
    float* el2s=(float*)(sm+18432);               // 18432
    float* al2s=(float*)(sm+36864);               // 512*12*4 = 24576
    float* lg1s=(float*)(sm+61440);               // 4096
    float* el1s=(float*)(sm+65536);               // 4096
    unsigned char* bp2=(unsigned char*)(sm+69632);// 4608
    uchar2* bp1=(uchar2*)(sm+74240);              // 1024
    unsigned char* vit1=(unsigned char*)(sm+75264);
    unsigned char* vit2=(unsigned char*)(sm+75776);
    float* tr2s=(float*)(sm+76288);               // 324
    __shared__ unsigned char map2[63],map1[14],ex2[8],ex1[8];
    __shared__ int s_last2,s_last1,s_isLast;
    __shared__ float s_ln1,s_ln2,s_g1,s_g2,sred[24];

    int b=blockIdx.x, sl=seqlen[b], tid=threadIdx.x, wid=tid>>5, lane=tid&31;
    const int* lab=label+b*T;

    const float* p2=g_lg2+b*T*9;
    for(int i=tid;i<T*9;i+=256){float v=p2[i]; lg2s[i]=v; el2s[i]=__expf(v);}
    const float* p1=g_lg1+b*T*2;
    for(int i=tid;i<T*2;i+=256){float v=p1[i]; lg1s[i]=v; el1s[i]=__expf(v);}
    for(int i=tid;i<81;i+=256) tr2s[i]=trans2[i];
    __syncthreads();

    if(wid==7){                       // ---- decode2 forward (exact), no inline argmax
        if(lane<9){
            int j=lane;
            float Tw[9];
#pragma unroll
            for(int i=0;i<9;i++)Tw[i]=tr2s[i*9+j];
            float v=lg2s[j];
            al2s[j]=v;
            for(int t=1;t<sl;++t){
                float lv=lg2s[t*9+j];
                float q0=__shfl_sync(M9,v,0)+Tw[0], q1=__shfl_sync(M9,v,1)+Tw[1];
                float q2=__shfl_sync(M9,v,2)+Tw[2], q3=__shfl_sync(M9,v,3)+Tw[3];
                float q4=__shfl_sync(M9,v,4)+Tw[4], q5=__shfl_sync(M9,v,5)+Tw[5];
                float q6=__shfl_sync(M9,v,6)+Tw[6], q7=__shfl_sync(M9,v,7)+Tw[7];
                float q8=__shfl_sync(M9,v,8)+Tw[8];
                float m=fmaxf(fmaxf(fmaxf(q0,q1),fmaxf(q2,q3)),fmaxf(fmaxf(q4,q5),fmaxf(q6,q7)));
                v=fmaxf(m,q8)+lv;
                al2s[t*12+j]=v;
            }
            float tot; int la=0; float best=-3.0e38f;
#pragma unroll
            for(int i=0;i<9;i++){tot=__shfl_sync(M9,v,i); if(tot>best){best=tot;la=i;}}
            if(j==0) s_last2=la;
        }
    } else if(wid==6){                // ---- lognorm2 (linear domain)
        if(lane<9){
            int j=lane;
            float E[9];
#pragma unroll
            for(int i=0;i<9;i++)E[i]=__expf(tr2s[i*9+j]);
            float a=el2s[j]; int Zi=0;
            for(int t=1;t<sl;++t){
                float el=el2s[t*9+j];
                float s0=__shfl_sync(M9,a,0)*E[0], s1=__shfl_sync(M9,a,1)*E[1];
                float s2=__shfl_sync(M9,a,2)*E[2], s3=__shfl_sync(M9,a,3)*E[3];
                float s4=__shfl_sync(M9,a,4)*E[4], s5=__shfl_sync(M9,a,5)*E[5];
                float s6=__shfl_sync(M9,a,6)*E[6], s7=__shfl_sync(M9,a,7)*E[7];
                float s8=__shfl_sync(M9,a,8)*E[8];
                a=(((s0+s1)+(s2+s3))+((s4+s5)+(s6+s7))+s8)*el;
                if((t&3)==0){
                    float r0=__shfl_sync(M9,a,0);
                    int eb=(__float_as_int(r0)>>23)&0xff;
                    a*=__int_as_float((254-eb)<<23); Zi+=eb-127;
                }
            }
            float tot=0.0f;
#pragma unroll
            for(int i=0;i<9;i++) tot+=__shfl_sync(M9,a,i);
            if(j==0) s_ln2=(float)Zi*0.6931471805599453f+__logf(tot);
        }
    } else if(wid==5){                // ---- decode1 (in-lane, exact)
        if(lane==0){
            float T00=trans1[0],T01=trans1[1],T10=trans1[2],T11=trans1[3];
            float a0=lg1s[0],a1=lg1s[1];
            for(int t=1;t<sl;++t){
                float2 lv=*(const float2*)(lg1s+2*t);
                float q00=a0+T00,q10=a1+T10,q01=a0+T01,q11=a1+T11;
                uchar2 bp; bp.x=(q10>q00)?1:0; bp.y=(q11>q01)?1:0;
                bp1[t]=bp;
                a0=fmaxf(q00,q10)+lv.x; a1=fmaxf(q01,q11)+lv.y;
            }
            s_last1=(a1>a0)?1:0;
        }
    } else if(wid==4){                // ---- lognorm1 (in-lane, linear)
        if(lane==0){
            float F00=__expf(trans1[0]),F01=__expf(trans1[1]),F10=__expf(trans1[2]),F11=__expf(trans1[3]);
            float a0=el1s[0],a1=el1s[1]; int Zi=0;
            for(int t=1;t<sl;++t){
                float2 e=*(const float2*)(el1s+2*t);
                float n0=(a0*F00+a1*F10)*e.x, n1=(a0*F01+a1*F11)*e.y;
                a0=n0; a1=n1;
                if((t&7)==0){
                    int eb=(__float_as_int(a0)>>23)&0xff;
                    float sc=__int_as_float((254-eb)<<23);
                    a0*=sc; a1*=sc; Zi+=eb-127;
                }
            }
            s_ln1=(float)Zi*0.6931471805599453f+__logf(a0+a1);
        }
    } else if(wid==3){                // ---- gold scores
        float s1=0.0f,s2=0.0f;
        for(int t=lane;t<sl;t+=32){
            int tg2=lab[t]; int tg1=(tg2>0)?1:0;
            s1+=lg1s[t*2+tg1]; s2+=lg2s[t*9+tg2];
            if(t>0){
                int tp2=lab[t-1]; int tp1=(tp2>0)?1:0;
                s1+=trans1[tp1*2+tg1]; s2+=tr2s[tp2*9+tg2];
            }
        }
#pragma unroll
        for(int o=16;o;o>>=1){s1+=__shfl_xor_sync(FULL,s1,o);s2+=__shfl_xor_sync(FULL,s2,o);}
        if(lane==0){s_g1=s1;s_g2=s2;}
    }
    __syncthreads();

    // ---- recompute bp2 in parallel from stored alphas (exact) ----
    for(int t=1+tid;t<sl;t+=256){
        const float4* ar=(const float4*)(al2s+(t-1)*12);
        float4 A=ar[0],Bv=ar[1],Cv=ar[2];
        float av[9]={A.x,A.y,A.z,A.w,Bv.x,Bv.y,Bv.z,Bv.w,Cv.x};
        unsigned char* bo=bp2+t*9;
#pragma unroll
        for(int j=0;j<9;j++){
            float q[9]; float m=-3.0e38f;
#pragma unroll
            for(int i=0;i<9;i++){q[i]=av[i]+tr2s[i*9+j]; m=fmaxf(m,q[i]);}
            int bp=8;
#pragma unroll
            for(int i=7;i>=0;i--) if(q[i]==m) bp=i;
            bo[j]=(unsigned char)bp;
        }
    }
    for(int t=sl+tid;t<T;t+=256){
        unsigned char* bo=bp2+t*9;
#pragma unroll
        for(int j=0;j<9;j++) bo[j]=(unsigned char)j;
        uchar2 e; e.x=0; e.y=1; bp1[t]=e;
    }
    __syncthreads();

    // ---- chunk tag-maps (exact pointer chases) ----
    if(tid<63){
        int c=1+tid/9, j=tid-(tid/9)*9;
        int hi=(c==7)?511:64*(c+1);
        int cur=j;
        for(int t=hi;t>64*c;--t) cur=bp2[t*9+cur];
        map2[(c-1)*9+j]=(unsigned char)cur;
    } else if(tid>=64&&tid<78){
        int c=1+(tid-64)/2, j=(tid-64)&1;
        int hi=(c==7)?511:64*(c+1);
        int cur=j;
        for(int t=hi;t>64*c;--t){uchar2 bp=bp1[t]; cur=cur?bp.y:bp.x;}
        map1[(c-1)*2+j]=(unsigned char)cur;
    }
    __syncthreads();
    if(tid==0){
        int e=s_last2; ex2[7]=(unsigned char)e;
        for(int c=7;c>=1;c--){e=map2[(c-1)*9+e]; ex2[c-1]=(unsigned char)e;}
    } else if(tid==32){
        int e=s_last1; ex1[7]=(unsigned char)e;
        for(int c=7;c>=1;c--){e=map1[(c-1)*2+e]; ex1[c-1]=(unsigned char)e;}
    }
    __syncthreads();
    if(tid<8){
        int c=tid; int hi=(c==7)?511:64*(c+1); int cur=ex2[c];
        if(c==7) vit2[511]=(unsigned char)cur;
        for(int t=hi;t>64*c;--t){cur=bp2[t*9+cur]; vit2[t-1]=(unsigned char)cur;}
    } else if(tid>=32&&tid<40){
        int c=tid-32; int hi=(c==7)?511:64*(c+1); int cur=ex1[c];
        if(c==7) vit1[511]=(unsigned char)cur;
        for(int t=hi;t>64*c;--t){uchar2 bp=bp1[t]; cur=cur?bp.y:bp.x; vit1[t-1]=(unsigned char)cur;}
    }
    __syncthreads();

    // ---- outputs + accuracy partials ----
    float c1=0.0f,c2=0.0f,cc=0.0f;
    for(int t=tid;t<T;t+=256){
        int v1=vit1[t],v2=vit2[t],lb=lab[t];
        int vv=v1?v2:0;
        out[b*T+t]=(float)vv;
        if(t<sl){
            c1+=(v1==((lb>0)?1:0))?1.0f:0.0f;
            c2+=(v2==lb)?1.0f:0.0f;
            cc+=(vv==lb)?1.0f:0.0f;
        }
    }
#pragma unroll
    for(int o=16;o;o>>=1){
        c1+=__shfl_xor_sync(FULL,c1,o);
        c2+=__shfl_xor_sync(FULL,c2,o);
        cc+=__shfl_xor_sync(FULL,cc,o);
    }
    if(lane==0){sred[wid]=c1;sred[8+wid]=c2;sred[16+wid]=cc;}
    __syncthreads();
    if(tid==0){
        float a1=0,a2=0,a3=0;
#pragma unroll
        for(int k=0;k<8;k++){a1+=sred[k];a2+=sred[8+k];a3+=sred[16+k];}
        g_c1[b]=a1; g_c2[b]=a2; g_cc[b]=a3;
        g_ll1[b]=s_g1-s_ln1; g_ll2[b]=s_g2-s_ln2;
        __threadfence();
        int v=atomicAdd(&g_ctr,1);
        s_isLast=(v==B-1)?1:0;
    }
    __syncthreads();

    if(s_isLast){
        __threadfence();
        int i=tid;
        float vals[6]={0,0,0,0,0,0};
        if(i<B){
            vals[0]=-g_ll1[i]; vals[1]=-g_ll2[i];
            vals[2]=g_c1[i]; vals[3]=g_c2[i]; vals[4]=g_cc[i];
            vals[5]=(float)seqlen[i];
        }
#pragma unroll
        for(int k=0;k<6;k++)
#pragma unroll
            for(int o=16;o;o>>=1) vals[k]+=__shfl_xor_sync(FULL,vals[k],o);
        __shared__ float sh2[2][6];
        if(i<B&&(i&31)==0)
#pragma unroll
            for(int k=0;k<6;k++) sh2[i>>5][k]=vals[k];
        __syncthreads();
        if(i==0){
            float S[6];
#pragma unroll
            for(int k=0;k<6;k++) S[k]=sh2[0][k]+sh2[1][k];
            float loss=(S[0]/(float)B+8.0f*(S[1]/(float)B))/9.0f;
            float tot=S[5];
            int base=out_size-4;
            out[base+0]=loss;
            out[base+1]=S[2]/tot;
            out[base+2]=S[3]/tot;
            out[base+3]=S[4]/tot;
            g_ctr=0;
        }
    }
}

extern "C" void kernel_launch(void* const* d_in, const int* in_sizes, int n_in,
                              void* d_out, int out_size) {
    const float* x      = (const float*)d_in[0];
    const int*   label  = (const int*)d_in[1];
    const int*   seqlen = (const int*)d_in[2];
    const float* W1     = (const float*)d_in[3];
    const float* b1     = (const float*)d_in[4];
    const float* W2     = (const float*)d_in[5];
    const float* b2     = (const float*)d_in[6];
    const float* trans1 = (const float*)d_in[7];
    const float* trans2 = (const float*)d_in[8];
    float* out = (float*)d_out;

    static int smem_set = 0;
    if(!smem_set){
        cudaFuncSetAttribute(scan_kernel, cudaFuncAttributeMaxDynamicSharedMemorySize, 76800);
        smem_set = 1;
    }
    gemm_kernel<<<(B*T)/32, 256>>>(x, W1, b1, W2, b2);
    scan_kernel<<<B, 256, 76800>>>(label, seqlen, trans1, trans2, out, out_size);
}